// round 4
// baseline (speedup 1.0000x reference)
#include <cuda_runtime.h>
#include <cuda_bf16.h>

// ---------------- problem constants ----------------
#define BB 8
#define SS 8192
#define DD 512
#define HH 512
#define OO 512
#define MM (BB*SS)        // 65536 rows
#define CHUNKS 64
#define CLEN (SS/CHUNKS)  // 128

// ---------------- scratch (no allocs allowed) ----------------
__device__ float g_a[MM*HH];               // coeff  c = sigmoid(-gate)
__device__ float g_b[MM*HH];               // value  v = sigmoid(gate)*G(hidden)
__device__ float g_h[MM*HH];               // hidden states h
__device__ float g_Ac[BB*CHUNKS*HH];       // per-chunk carry A
__device__ float g_Bc[BB*CHUNKS*HH];       // per-chunk carry B
__device__ float g_H0[BB*CHUNKS*HH];       // h at chunk start

// ---------------- bf16 split helpers ----------------
__device__ __forceinline__ void split_pair(float x, float y,
                                           unsigned& hi, unsigned& lo)
{
    __nv_bfloat16 xh = __float2bfloat16(x);
    __nv_bfloat16 yh = __float2bfloat16(y);
    __nv_bfloat16 xl = __float2bfloat16(x - __bfloat162float(xh));
    __nv_bfloat16 yl = __float2bfloat16(y - __bfloat162float(yh));
    __nv_bfloat162 h2 = __halves2bfloat162(xh, yh);
    __nv_bfloat162 l2 = __halves2bfloat162(xl, yl);
    hi = *reinterpret_cast<unsigned*>(&h2);
    lo = *reinterpret_cast<unsigned*>(&l2);
}

__device__ __forceinline__ void mma_bf16(float& d0, float& d1, float& d2, float& d3,
                                         unsigned a0, unsigned a1, unsigned a2, unsigned a3,
                                         unsigned b0, unsigned b1)
{
    asm volatile(
        "mma.sync.aligned.m16n8k16.row.col.f32.bf16.bf16.f32 "
        "{%0,%1,%2,%3}, {%4,%5,%6,%7}, {%8,%9}, {%0,%1,%2,%3};\n"
        : "+f"(d0), "+f"(d1), "+f"(d2), "+f"(d3)
        : "r"(a0), "r"(a1), "r"(a2), "r"(a3), "r"(b0), "r"(b1));
}

// Tiling (both GEMMs): CTA = 256 threads (8 warps), tile 128(M) x 64(N), BK=16.
// Warp grid 4(m) x 2(n), warp tile 32x32 -> MF=2 m-frags, NF=4 n-frags.
#define BK 16
#define SPAD 24              // padded row stride in bf16 elems (48B, conflict-free)

// =====================================================================
// GEMM1: hg = x @ W_hg^T (bf16-split tensor core), fused activation.
// CTA tile covers 64 interleaved cols: even j -> hidden row (hb + j/2),
// odd j -> gate row (512 + hb + j/2).  grid = (16 nTiles, 512 mTiles)
// =====================================================================
__global__ __launch_bounds__(256, 2) void gemm1_act(const float* __restrict__ X,
                                                    const float* __restrict__ W)
{
    __shared__ __align__(16) unsigned short Ah[128][SPAD], Al[128][SPAD];
    __shared__ __align__(16) unsigned short Bh[64][SPAD],  Bl[64][SPAD];

    const int tid = threadIdx.x;
    const int m0  = blockIdx.y * 128;
    const int hb  = blockIdx.x * 32;          // h-column base (32 h per CTA)

    const int lane = tid & 31;
    const int wid  = tid >> 5;
    const int wm   = wid & 3;                 // 4 warp rows (32 each)
    const int wn   = wid >> 2;                // 2 warp cols (32 each)
    const int g    = lane >> 2;               // 0..7
    const int tg   = lane & 3;                // 0..3

    // gmem staging: A 2 float4/thread, B 1 float4/thread
    const int arow0 = tid >> 2,        ac4_0 = tid & 3;           // fa = tid
    const int arow1 = (tid + 256) >> 2, ac4_1 = tid & 3;          // fa = tid+256
    const int brow  = tid >> 2,        bc4   = tid & 3;
    const int be    = (brow & 1) ? (HH + hb + (brow >> 1)) : (hb + (brow >> 1));

    float4 pa0, pa1, pb;
    auto ldg = [&](int kt) {
        const float* xp = X + (long long)(m0)*DD + kt*BK;
        pa0 = *(const float4*)&xp[(long long)arow0*DD + ac4_0*4];
        pa1 = *(const float4*)&xp[(long long)arow1*DD + ac4_1*4];
        pb  = *(const float4*)&W[(long long)be*DD + kt*BK + bc4*4];
    };
    auto stg = [&]() {
        unsigned h0,l0,h1,l1;
        split_pair(pa0.x, pa0.y, h0, l0); split_pair(pa0.z, pa0.w, h1, l1);
        *(unsigned*)&Ah[arow0][ac4_0*4]   = h0; *(unsigned*)&Ah[arow0][ac4_0*4+2] = h1;
        *(unsigned*)&Al[arow0][ac4_0*4]   = l0; *(unsigned*)&Al[arow0][ac4_0*4+2] = l1;
        split_pair(pa1.x, pa1.y, h0, l0); split_pair(pa1.z, pa1.w, h1, l1);
        *(unsigned*)&Ah[arow1][ac4_1*4]   = h0; *(unsigned*)&Ah[arow1][ac4_1*4+2] = h1;
        *(unsigned*)&Al[arow1][ac4_1*4]   = l0; *(unsigned*)&Al[arow1][ac4_1*4+2] = l1;
        split_pair(pb.x, pb.y, h0, l0);   split_pair(pb.z, pb.w, h1, l1);
        *(unsigned*)&Bh[brow][bc4*4]      = h0; *(unsigned*)&Bh[brow][bc4*4+2]    = h1;
        *(unsigned*)&Bl[brow][bc4*4]      = l0; *(unsigned*)&Bl[brow][bc4*4+2]    = l1;
    };

    float acc[2][4][4];
    #pragma unroll
    for (int i = 0; i < 2; ++i)
        #pragma unroll
        for (int j = 0; j < 4; ++j)
            #pragma unroll
            for (int q = 0; q < 4; ++q) acc[i][j][q] = 0.f;

    ldg(0);
    const int KT = DD / BK;   // 32
    for (int kt = 0; kt < KT; ++kt) {
        stg();
        __syncthreads();
        if (kt + 1 < KT) ldg(kt + 1);

        unsigned ah[2][4], al[2][4], bh[4][2], bl[4][2];
        #pragma unroll
        for (int fm = 0; fm < 2; ++fm) {
            int r = wm*32 + fm*16 + g;
            ah[fm][0] = *(const unsigned*)&Ah[r  ][2*tg];
            ah[fm][1] = *(const unsigned*)&Ah[r+8][2*tg];
            ah[fm][2] = *(const unsigned*)&Ah[r  ][2*tg+8];
            ah[fm][3] = *(const unsigned*)&Ah[r+8][2*tg+8];
            al[fm][0] = *(const unsigned*)&Al[r  ][2*tg];
            al[fm][1] = *(const unsigned*)&Al[r+8][2*tg];
            al[fm][2] = *(const unsigned*)&Al[r  ][2*tg+8];
            al[fm][3] = *(const unsigned*)&Al[r+8][2*tg+8];
        }
        #pragma unroll
        for (int nf = 0; nf < 4; ++nf) {
            int c = wn*32 + nf*8 + g;
            bh[nf][0] = *(const unsigned*)&Bh[c][2*tg];
            bh[nf][1] = *(const unsigned*)&Bh[c][2*tg+8];
            bl[nf][0] = *(const unsigned*)&Bl[c][2*tg];
            bl[nf][1] = *(const unsigned*)&Bl[c][2*tg+8];
        }
        #pragma unroll
        for (int fm = 0; fm < 2; ++fm)
            #pragma unroll
            for (int nf = 0; nf < 4; ++nf) {
                float* d = acc[fm][nf];
                mma_bf16(d[0],d[1],d[2],d[3], ah[fm][0],ah[fm][1],ah[fm][2],ah[fm][3], bh[nf][0],bh[nf][1]);
                mma_bf16(d[0],d[1],d[2],d[3], ah[fm][0],ah[fm][1],ah[fm][2],ah[fm][3], bl[nf][0],bl[nf][1]);
                mma_bf16(d[0],d[1],d[2],d[3], al[fm][0],al[fm][1],al[fm][2],al[fm][3], bh[nf][0],bh[nf][1]);
            }
        __syncthreads();
    }

    // activation epilogue: (c0,c1) = (hidden,gate) at row r; (c2,c3) at row r+8
    #pragma unroll
    for (int fm = 0; fm < 2; ++fm) {
        #pragma unroll
        for (int nf = 0; nf < 4; ++nf) {
            int hcol = hb + wn*16 + nf*4 + tg;
            int r0 = m0 + wm*32 + fm*16 + g;
            #pragma unroll
            for (int half = 0; half < 2; ++half) {
                int m  = r0 + half*8;
                float hid = acc[fm][nf][2*half];
                float gat = acc[fm][nf][2*half+1];
                float eg = __expf(gat);
                float cc = 1.f / (1.f + eg);          // sigmoid(-gate)
                float sg = 1.f - cc;                  // sigmoid(gate)
                float G  = (hid >= 0.f) ? (hid + 0.5f)
                                        : (1.f / (1.f + __expf(-hid)));
                g_a[(long long)m*HH + hcol] = cc;
                g_b[(long long)m*HH + hcol] = sg * G;
            }
        }
    }
}

// =====================================================================
// Scan phase 1: per (b, h, chunk) carry (A,B):  h_out = A*h_in + B
// =====================================================================
__global__ __launch_bounds__(256) void scan_phase1()
{
    int c  = blockIdx.x;
    int b  = blockIdx.z;
    int hh = blockIdx.y*256 + threadIdx.x;
    int base = (b*SS + c*CLEN)*HH + hh;
    const float* ap = g_a + base;
    const float* bp = g_b + base;
    float A = 1.f, Bv = 0.f;
    #pragma unroll 8
    for (int s = 0; s < CLEN; ++s) {
        float av = ap[(long long)s*HH];
        float bv = bp[(long long)s*HH];
        Bv = av*Bv + bv;
        A  = A*av;
    }
    int ci = (b*CHUNKS + c)*HH + hh;
    g_Ac[ci] = A;
    g_Bc[ci] = Bv;
}

// =====================================================================
// Scan phase 2: sequential over chunks per channel
// =====================================================================
__global__ __launch_bounds__(256) void scan_phase2()
{
    int t = blockIdx.x*256 + threadIdx.x;     // 0..4095
    int b = t >> 9, hh = t & 511;
    float run = 0.f;
    for (int c = 0; c < CHUNKS; ++c) {
        int ci = (b*CHUNKS + c)*HH + hh;
        g_H0[ci] = run;
        run = g_Ac[ci]*run + g_Bc[ci];
    }
}

// =====================================================================
// Scan phase 3: re-run recurrence within chunk, write h
// =====================================================================
__global__ __launch_bounds__(256) void scan_phase3()
{
    int c  = blockIdx.x;
    int b  = blockIdx.z;
    int hh = blockIdx.y*256 + threadIdx.x;
    int base = (b*SS + c*CLEN)*HH + hh;
    const float* ap = g_a + base;
    const float* bp = g_b + base;
    float* hp = g_h + base;
    float h = g_H0[(b*CHUNKS + c)*HH + hh];
    #pragma unroll 8
    for (int s = 0; s < CLEN; ++s) {
        h = ap[(long long)s*HH]*h + bp[(long long)s*HH];
        hp[(long long)s*HH] = h;
    }
}

// =====================================================================
// GEMM2: out = h @ W_out^T  (bf16-split tensor core)
// grid = (8 nTiles, 512 mTiles)
// =====================================================================
__global__ __launch_bounds__(256, 2) void gemm2_out(const float* __restrict__ W,
                                                    float* __restrict__ out)
{
    __shared__ __align__(16) unsigned short Ah[128][SPAD], Al[128][SPAD];
    __shared__ __align__(16) unsigned short Bh[64][SPAD],  Bl[64][SPAD];

    const int tid = threadIdx.x;
    const int m0  = blockIdx.y * 128;
    const int n0  = blockIdx.x * 64;

    const int lane = tid & 31;
    const int wid  = tid >> 5;
    const int wm   = wid & 3;
    const int wn   = wid >> 2;
    const int g    = lane >> 2;
    const int tg   = lane & 3;

    const int arow0 = tid >> 2,         ac4_0 = tid & 3;
    const int arow1 = (tid + 256) >> 2, ac4_1 = tid & 3;
    const int brow  = tid >> 2,         bc4   = tid & 3;

    float4 pa0, pa1, pb;
    auto ldg = [&](int kt) {
        const float* xp = g_h + (long long)(m0)*HH + kt*BK;
        pa0 = *(const float4*)&xp[(long long)arow0*HH + ac4_0*4];
        pa1 = *(const float4*)&xp[(long long)arow1*HH + ac4_1*4];
        pb  = *(const float4*)&W[(long long)(n0 + brow)*HH + kt*BK + bc4*4];
    };
    auto stg = [&]() {
        unsigned h0,l0,h1,l1;
        split_pair(pa0.x, pa0.y, h0, l0); split_pair(pa0.z, pa0.w, h1, l1);
        *(unsigned*)&Ah[arow0][ac4_0*4]   = h0; *(unsigned*)&Ah[arow0][ac4_0*4+2] = h1;
        *(unsigned*)&Al[arow0][ac4_0*4]   = l0; *(unsigned*)&Al[arow0][ac4_0*4+2] = l1;
        split_pair(pa1.x, pa1.y, h0, l0); split_pair(pa1.z, pa1.w, h1, l1);
        *(unsigned*)&Ah[arow1][ac4_1*4]   = h0; *(unsigned*)&Ah[arow1][ac4_1*4+2] = h1;
        *(unsigned*)&Al[arow1][ac4_1*4]   = l0; *(unsigned*)&Al[arow1][ac4_1*4+2] = l1;
        split_pair(pb.x, pb.y, h0, l0);   split_pair(pb.z, pb.w, h1, l1);
        *(unsigned*)&Bh[brow][bc4*4]      = h0; *(unsigned*)&Bh[brow][bc4*4+2]    = h1;
        *(unsigned*)&Bl[brow][bc4*4]      = l0; *(unsigned*)&Bl[brow][bc4*4+2]    = l1;
    };

    float acc[2][4][4];
    #pragma unroll
    for (int i = 0; i < 2; ++i)
        #pragma unroll
        for (int j = 0; j < 4; ++j)
            #pragma unroll
            for (int q = 0; q < 4; ++q) acc[i][j][q] = 0.f;

    ldg(0);
    const int KT = HH / BK;   // 32
    for (int kt = 0; kt < KT; ++kt) {
        stg();
        __syncthreads();
        if (kt + 1 < KT) ldg(kt + 1);

        unsigned ah[2][4], al[2][4], bh[4][2], bl[4][2];
        #pragma unroll
        for (int fm = 0; fm < 2; ++fm) {
            int r = wm*32 + fm*16 + g;
            ah[fm][0] = *(const unsigned*)&Ah[r  ][2*tg];
            ah[fm][1] = *(const unsigned*)&Ah[r+8][2*tg];
            ah[fm][2] = *(const unsigned*)&Ah[r  ][2*tg+8];
            ah[fm][3] = *(const unsigned*)&Ah[r+8][2*tg+8];
            al[fm][0] = *(const unsigned*)&Al[r  ][2*tg];
            al[fm][1] = *(const unsigned*)&Al[r+8][2*tg];
            al[fm][2] = *(const unsigned*)&Al[r  ][2*tg+8];
            al[fm][3] = *(const unsigned*)&Al[r+8][2*tg+8];
        }
        #pragma unroll
        for (int nf = 0; nf < 4; ++nf) {
            int c = wn*32 + nf*8 + g;
            bh[nf][0] = *(const unsigned*)&Bh[c][2*tg];
            bh[nf][1] = *(const unsigned*)&Bh[c][2*tg+8];
            bl[nf][0] = *(const unsigned*)&Bl[c][2*tg];
            bl[nf][1] = *(const unsigned*)&Bl[c][2*tg+8];
        }
        #pragma unroll
        for (int fm = 0; fm < 2; ++fm)
            #pragma unroll
            for (int nf = 0; nf < 4; ++nf) {
                float* d = acc[fm][nf];
                mma_bf16(d[0],d[1],d[2],d[3], ah[fm][0],ah[fm][1],ah[fm][2],ah[fm][3], bh[nf][0],bh[nf][1]);
                mma_bf16(d[0],d[1],d[2],d[3], ah[fm][0],ah[fm][1],ah[fm][2],ah[fm][3], bl[nf][0],bl[nf][1]);
                mma_bf16(d[0],d[1],d[2],d[3], al[fm][0],al[fm][1],al[fm][2],al[fm][3], bh[nf][0],bh[nf][1]);
            }
        __syncthreads();
    }

    #pragma unroll
    for (int fm = 0; fm < 2; ++fm) {
        #pragma unroll
        for (int nf = 0; nf < 4; ++nf) {
            int cc = n0 + wn*32 + nf*8 + 2*tg;
            int r0 = m0 + wm*32 + fm*16 + g;
            float2 v0 = make_float2(acc[fm][nf][0], acc[fm][nf][1]);
            float2 v1 = make_float2(acc[fm][nf][2], acc[fm][nf][3]);
            *(float2*)&out[(long long)r0*OO + cc]       = v0;
            *(float2*)&out[(long long)(r0+8)*OO + cc]   = v1;
        }
    }
}

// =====================================================================
// h_n copy: last timestep of h -> tail of output buffer
// =====================================================================
__global__ void copy_hn(float* __restrict__ out)
{
    int t = blockIdx.x*256 + threadIdx.x;     // 0..4095
    int b = t >> 9, hh = t & 511;
    out[(long long)MM*OO + t] = g_h[((long long)b*SS + (SS-1))*HH + hh];
}

// =====================================================================
// launch
// =====================================================================
extern "C" void kernel_launch(void* const* d_in, const int* in_sizes, int n_in,
                              void* d_out, int out_size)
{
    const float* x    = (const float*)d_in[0];
    // d_in[1] = is_init : unused by the reference (all false)
    const float* Whg  = (const float*)d_in[2];
    const float* Wout = (const float*)d_in[3];
    float* out = (float*)d_out;

    gemm1_act<<<dim3(16, MM/128), 256>>>(x, Whg);          // x = N-tiles for L2 reuse
    scan_phase1<<<dim3(CHUNKS, HH/256, BB), 256>>>();
    scan_phase2<<<16, 256>>>();
    scan_phase3<<<dim3(CHUNKS, HH/256, BB), 256>>>();
    gemm2_out<<<dim3(8, MM/128), 256>>>(Wout, out);

    long long need = (long long)MM*OO + (long long)BB*HH;
    if ((long long)out_size >= need)
        copy_hn<<<16, 256>>>(out);
}